// round 10
// baseline (speedup 1.0000x reference)
#include <cuda_runtime.h>
#include <cstdint>

// Sparsemax over rows of 16384 x 4096 fp32.
// Persistent CTAs. Row prefetch via ONE cp.async.bulk (TMA, async proxy)
// per row into a shared double buffer, completion via mbarrier expect_tx:
// removes the 16-LDGSTS-per-thread issue cost that co-limited with DRAM.
// Exact sort-free tau: candidates {x > rowmax-1} + Michelot fixed point,
// iteration 1 fused into the gather (block S, C -> t1=(S-1)/C); tiny
// residual iterations run redundantly per warp. Full-row fallback on
// candidate overflow keeps correctness unconditional.

#define N_COLS      4096
#define ROW_BYTES   (N_COLS * 4)
#define THREADS     256
#define CAND_CAP    1024
#define CTAS_PER_SM 6
#define NBLOCKS     (152 * CTAS_PER_SM)   // one persistent wave on GB300

__device__ __forceinline__ unsigned enc_f(float f) {
    unsigned u = __float_as_uint(f);
    return (u & 0x80000000u) ? ~u : (u | 0x80000000u);   // order-preserving
}
__device__ __forceinline__ float dec_f(unsigned e) {
    unsigned u = (e & 0x80000000u) ? (e & 0x7fffffffu) : ~e;
    return __uint_as_float(u);
}

__device__ __forceinline__ uint32_t sh_addr(const void* p) {
    return (uint32_t)__cvta_generic_to_shared(p);
}

__device__ __forceinline__ void mbar_init(uint32_t mb, uint32_t count) {
    asm volatile("mbarrier.init.shared.b64 [%0], %1;" :: "r"(mb), "r"(count) : "memory");
}

__device__ __forceinline__ void tma_row(uint32_t dst_sh, const void* gsrc, uint32_t mb) {
    asm volatile("mbarrier.arrive.expect_tx.shared.b64 _, [%0], %1;"
                 :: "r"(mb), "r"((uint32_t)ROW_BYTES) : "memory");
    asm volatile("cp.async.bulk.shared::cluster.global.mbarrier::complete_tx::bytes "
                 "[%0], [%1], %2, [%3];"
                 :: "r"(dst_sh), "l"(gsrc), "r"((uint32_t)ROW_BYTES), "r"(mb) : "memory");
}

__device__ __forceinline__ void mbar_wait(uint32_t mb, uint32_t phase) {
    asm volatile(
        "{\n\t"
        ".reg .pred P1;\n\t"
        "WAIT_LOOP_%=:\n\t"
        "mbarrier.try_wait.parity.acquire.cta.shared::cta.b64 P1, [%0], %1, 0x989680;\n\t"
        "@P1 bra.uni WAIT_DONE_%=;\n\t"
        "bra.uni WAIT_LOOP_%=;\n\t"
        "WAIT_DONE_%=:\n\t"
        "}"
        :: "r"(mb), "r"(phase) : "memory");
}

__global__ __launch_bounds__(THREADS, CTAS_PER_SM)
void sparsemax_kernel(const float* __restrict__ x, float* __restrict__ out,
                      int rows) {
    __shared__ __align__(128) float buf[2][N_COLS];   // 32 KB double buffer
    __shared__ float              cand[CAND_CAP];     // 4 KB
    __shared__ unsigned           sh_maxbits[2];      // parity-buffered
    __shared__ int                sh_cnt[2];
    __shared__ float              sh_sum[2];
    __shared__ __align__(8) unsigned long long mbar[2];

    const int tid    = threadIdx.x;
    const int lane   = tid & 31;
    const int stride = gridDim.x;
    const uint32_t mb0 = sh_addr(&mbar[0]);
    const uint32_t mb1 = sh_addr(&mbar[1]);

    // ---- prologue: init mbarriers + counter slots ----
    if (tid == 0) {
        mbar_init(mb0, 1);
        mbar_init(mb1, 1);
        sh_maxbits[0] = 0u; sh_maxbits[1] = 0u;
        sh_cnt[0] = 0;      sh_cnt[1] = 0;
        sh_sum[0] = 0.0f;   sh_sum[1] = 0.0f;
    }
    __syncthreads();   // mbarriers visible before first TMA

    const int r0 = blockIdx.x;
    if (tid == 0 && r0 < rows)
        tma_row(sh_addr(&buf[0][0]), x + (size_t)r0 * N_COLS, mb0);

    int it = 0;        // iteration counter: slot = it&1, phase = (it>>1)&1
    for (int r = r0; r < rows; r += stride, it++) {
        const int p = it & 1;
        const uint32_t mb_p  = p ? mb1 : mb0;
        const uint32_t mb_np = p ? mb0 : mb1;

        // ---- issue next row's TMA into slot p^1 (overlaps this row) ----
        // slot p^1 buffer + mbarrier: all threads finished with them at
        // iter-2, separated from here by two __syncthreads rendezvous.
        const int rn = r + stride;
        if (tid == 0 && rn < rows)
            tma_row(sh_addr(&buf[p ^ 1][0]), x + (size_t)rn * N_COLS, mb_np);

        // ---- wait for this row's data (acquire) ----
        mbar_wait(mb_p, (it >> 1) & 1);

        const float4* b = reinterpret_cast<const float4*>(&buf[p][0]);

        // ---- single shared read: row into registers; warp max + REDUX ----
        float4 v[4];
        float m = -3.402823466e38f;
#pragma unroll
        for (int k = 0; k < 4; k++) {
            v[k] = b[tid + k * THREADS];
            m = fmaxf(m, fmaxf(fmaxf(v[k].x, v[k].y), fmaxf(v[k].z, v[k].w)));
        }
        unsigned we = __reduce_max_sync(0xffffffffu, enc_f(m));
        if (lane == 0) atomicMax(&sh_maxbits[p], we);
        __syncthreads();                                     // B2 (rendezvous)

        const float thresh = dec_f(sh_maxbits[p]) - 1.0f;   // tau* >= thresh

        // reset slot p^1 state for its next use: its last readers all
        // passed B2 (they read at iter-1 before reaching this barrier);
        // its next writers are ordered after B3 below.
        if (tid == 0) {
            sh_maxbits[p ^ 1] = 0u;
            sh_cnt[p ^ 1] = 0;
            sh_sum[p ^ 1] = 0.0f;
        }

        // ---- gather candidates + fused Michelot iteration 1 (S, C) ----
        float s_part = 0.0f;
#pragma unroll
        for (int k = 0; k < 4; k++) {
            float vals[4] = {v[k].x, v[k].y, v[k].z, v[k].w};
#pragma unroll
            for (int j = 0; j < 4; j++) {
                if (vals[j] > thresh) {
                    s_part += vals[j];
                    int q = atomicAdd(&sh_cnt[p], 1);
                    if (q < CAND_CAP) cand[q] = vals[j];
                }
            }
        }
#pragma unroll
        for (int o = 16; o > 0; o >>= 1)
            s_part += __shfl_xor_sync(0xffffffffu, s_part, o);
        if (lane == 0) atomicAdd(&sh_sum[p], s_part);
        __syncthreads();                                     // B3 (rendezvous)

        // ---- residual Michelot (redundant per warp; usually 1-2 iters) ----
        float tau;
        {
            const int   C = sh_cnt[p];                 // exact even on overflow
            const float S = sh_sum[p];                 // exact even on overflow
            const float* src = cand;
            int nn = C;
            if (C > CAND_CAP) { nn = N_COLS; src = &buf[p][0]; }  // rare, exact
            float t = (S - 1.0f) / (float)C;           // Michelot iterate 1
            int c_prev = C;
            for (;;) {
                float s = 0.0f;
                int   c = 0;
                for (int i = lane; i < nn; i += 32) {
                    float z = src[i];
                    if (z > t) { s += z; c++; }
                }
#pragma unroll
                for (int o = 16; o > 0; o >>= 1)
                    s += __shfl_xor_sync(0xffffffffu, s, o);
                c = __reduce_add_sync(0xffffffffu, c);
                if (c == c_prev) break;        // support stabilized -> exact tau
                t = (s - 1.0f) / (float)c;     // c >= 1 (rowmax in support)
                c_prev = c;
            }
            tau = t;
        }

        // ---- output straight from registers, streaming stores ----
        float4* orow = reinterpret_cast<float4*>(out + (size_t)r * N_COLS);
#pragma unroll
        for (int k = 0; k < 4; k++) {
            float4 o;
            o.x = fmaxf(v[k].x - tau, 0.0f);
            o.y = fmaxf(v[k].y - tau, 0.0f);
            o.z = fmaxf(v[k].z - tau, 0.0f);
            o.w = fmaxf(v[k].w - tau, 0.0f);
            __stcs(&orow[tid + k * THREADS], o);
        }
    }
}

extern "C" void kernel_launch(void* const* d_in, const int* in_sizes, int n_in,
                              void* d_out, int out_size) {
    const float* x = (const float*)d_in[0];
    float* out = (float*)d_out;
    const int rows = in_sizes[0] / N_COLS;   // 16384
    sparsemax_kernel<<<NBLOCKS, THREADS>>>(x, out, rows);
}

// round 11
// speedup vs baseline: 1.0559x; 1.0559x over previous
#include <cuda_runtime.h>
#include <cstdint>

// Sparsemax over rows of 16384 x 4096 fp32.
// Persistent CTAs; next row prefetched via cp.async (LDGSTS) into a shared
// double buffer. Row is read from shared ONCE into registers; output is
// computed from registers. Exact sort-free tau:
//   candidates {x > rowmax-1}  (true support always a subset)
//   Michelot iterate 1 fused into the gather (block S, C -> t1=(S-1)/C)
//   warp 0 runs the tiny residual fixed-point (usually 1 iteration) and
//   broadcasts tau; other warps wait at one barrier (cheaper than the
//   redundant-all-warps variant, measured R3 vs R5-R9).
// Full-row fallback from shared on candidate overflow: correctness holds
// for any input.

#define N_COLS      4096
#define THREADS     256
#define CAND_CAP    1024
#define CTAS_PER_SM 6
#define NBLOCKS     (152 * CTAS_PER_SM)   // one persistent wave on GB300

__device__ __forceinline__ unsigned enc_f(float f) {
    unsigned u = __float_as_uint(f);
    return (u & 0x80000000u) ? ~u : (u | 0x80000000u);   // order-preserving
}
__device__ __forceinline__ float dec_f(unsigned e) {
    unsigned u = (e & 0x80000000u) ? (e & 0x7fffffffu) : ~e;
    return __uint_as_float(u);
}

__global__ __launch_bounds__(THREADS, CTAS_PER_SM)
void sparsemax_kernel(const float* __restrict__ x, float* __restrict__ out,
                      int rows) {
    __shared__ float    buf[2][N_COLS];     // 32 KB double buffer
    __shared__ float    cand[CAND_CAP];     // 4 KB
    __shared__ unsigned sh_maxbits[2];      // parity-buffered block state
    __shared__ int      sh_cnt[2];
    __shared__ float    sh_sum[2];
    __shared__ float    sh_tau;

    const int tid    = threadIdx.x;
    const int lane   = tid & 31;
    const int wid    = tid >> 5;
    const int stride = gridDim.x;

    // ---- prologue: init both state slots, prefetch first row ----
    if (tid == 0) {
        sh_maxbits[0] = 0u; sh_maxbits[1] = 0u;
        sh_cnt[0] = 0;      sh_cnt[1] = 0;
        sh_sum[0] = 0.0f;   sh_sum[1] = 0.0f;
    }
    int r0 = blockIdx.x;
    if (r0 < rows) {
        const float4* g = reinterpret_cast<const float4*>(x + (size_t)r0 * N_COLS);
        uint32_t s = (uint32_t)__cvta_generic_to_shared(&buf[0][0]);
#pragma unroll
        for (int k = 0; k < 4; k++) {
            uint32_t saddr = s + (uint32_t)(tid + k * THREADS) * 16u;
            asm volatile("cp.async.cg.shared.global [%0], [%1], 16;\n"
                         :: "r"(saddr), "l"(g + tid + k * THREADS));
        }
    }
    asm volatile("cp.async.commit_group;\n" ::: "memory");

    int p = 0;
    for (int r = r0; r < rows; r += stride, p ^= 1) {
        // ---- prefetch next row into buf[p^1] (overlaps this row's tau) ----
        const int rn = r + stride;
        if (rn < rows) {
            const float4* g = reinterpret_cast<const float4*>(x + (size_t)rn * N_COLS);
            uint32_t s = (uint32_t)__cvta_generic_to_shared(&buf[p ^ 1][0]);
#pragma unroll
            for (int k = 0; k < 4; k++) {
                uint32_t saddr = s + (uint32_t)(tid + k * THREADS) * 16u;
                asm volatile("cp.async.cg.shared.global [%0], [%1], 16;\n"
                             :: "r"(saddr), "l"(g + tid + k * THREADS));
            }
        }
        asm volatile("cp.async.commit_group;\n" ::: "memory");

        // wait for buf[p] (older group), leave the prefetch in flight
        asm volatile("cp.async.wait_group 1;\n" ::: "memory");
        __syncthreads();                                     // B1

        // reset the OTHER parity's state for its next use; every previous
        // reader of slot p^1 passed B1, every future writer is behind B2.
        if (tid == 0) {
            sh_maxbits[p ^ 1] = 0u;
            sh_cnt[p ^ 1] = 0;
            sh_sum[p ^ 1] = 0.0f;
        }

        const float4* b = reinterpret_cast<const float4*>(&buf[p][0]);

        // ---- single shared read: row into registers; REDUX warp max ----
        float4 v[4];
        float m = -3.402823466e38f;
#pragma unroll
        for (int k = 0; k < 4; k++) {
            v[k] = b[tid + k * THREADS];
            m = fmaxf(m, fmaxf(fmaxf(v[k].x, v[k].y), fmaxf(v[k].z, v[k].w)));
        }
        unsigned we = __reduce_max_sync(0xffffffffu, enc_f(m));
        if (lane == 0) atomicMax(&sh_maxbits[p], we);
        __syncthreads();                                     // B2

        const float thresh = dec_f(sh_maxbits[p]) - 1.0f;   // tau* >= thresh

        // ---- gather candidates + fused Michelot iteration 1 (S, C) ----
        float s_part = 0.0f;
#pragma unroll
        for (int k = 0; k < 4; k++) {
            float vals[4] = {v[k].x, v[k].y, v[k].z, v[k].w};
#pragma unroll
            for (int j = 0; j < 4; j++) {
                if (vals[j] > thresh) {
                    s_part += vals[j];
                    int q = atomicAdd(&sh_cnt[p], 1);
                    if (q < CAND_CAP) cand[q] = vals[j];
                }
            }
        }
#pragma unroll
        for (int o = 16; o > 0; o >>= 1)
            s_part += __shfl_xor_sync(0xffffffffu, s_part, o);
        if (lane == 0) atomicAdd(&sh_sum[p], s_part);
        __syncthreads();                                     // B3

        // ---- warp 0 only: residual Michelot (usually 1 short iteration) ----
        if (wid == 0) {
            const int   C = sh_cnt[p];                 // exact even on overflow
            const float S = sh_sum[p];                 // exact even on overflow
            const float* src = cand;
            int nn = C;
            if (C > CAND_CAP) { nn = N_COLS; src = &buf[p][0]; }  // rare, exact
            float t = (S - 1.0f) / (float)C;           // Michelot iterate 1
            int c_prev = C;
            for (;;) {
                float s = 0.0f;
                int   c = 0;
                for (int i = lane; i < nn; i += 32) {
                    float z = src[i];
                    if (z > t) { s += z; c++; }
                }
#pragma unroll
                for (int o = 16; o > 0; o >>= 1)
                    s += __shfl_xor_sync(0xffffffffu, s, o);
                c = __reduce_add_sync(0xffffffffu, c);
                if (c == c_prev) break;        // support stabilized -> exact tau
                t = (s - 1.0f) / (float)c;     // c >= 1 (rowmax in support)
                c_prev = c;
            }
            if (lane == 0) sh_tau = t;
        }
        __syncthreads();                                     // B4
        const float tau = sh_tau;

        // ---- output straight from registers, streaming stores ----
        float4* orow = reinterpret_cast<float4*>(out + (size_t)r * N_COLS);
#pragma unroll
        for (int k = 0; k < 4; k++) {
            float4 o;
            o.x = fmaxf(v[k].x - tau, 0.0f);
            o.y = fmaxf(v[k].y - tau, 0.0f);
            o.z = fmaxf(v[k].z - tau, 0.0f);
            o.w = fmaxf(v[k].w - tau, 0.0f);
            __stcs(&orow[tid + k * THREADS], o);
        }
    }
}

extern "C" void kernel_launch(void* const* d_in, const int* in_sizes, int n_in,
                              void* d_out, int out_size) {
    const float* x = (const float*)d_in[0];
    float* out = (float*)d_out;
    const int rows = in_sizes[0] / N_COLS;   // 16384
    sparsemax_kernel<<<NBLOCKS, THREADS>>>(x, out, rows);
}